// round 4
// baseline (speedup 1.0000x reference)
#include <cuda_runtime.h>
#include <cuda_bf16.h>
#include <math.h>

// Problem constants (fixed by the dataset)
constexpr int NN  = 50000;   // nodes
constexpr int F   = 256;     // hidden
constexpr int Hh  = 8;       // heads
constexpr int DHd = 32;      // per-head dim
constexpr int EE  = 800000;  // edges per metapath
constexpr int PP  = 3;       // metapaths
constexpr int F1  = 128;     // MLP hidden

// ---------------- scratch (device globals; no allocation allowed) ----------
__device__ __align__(16) float g_h0 [NN * F];
__device__ __align__(16) float g_h  [NN * F];
__device__ __align__(16) float g_hp [NN * F];
__device__ __align__(16) float g_acc[NN * F];
__device__ __align__(16) float g_ssrc[NN * Hh];
__device__ __align__(16) float g_sdst[NN * Hh];
__device__ __align__(16) float g_m  [NN * Hh];
__device__ __align__(16) float g_den[NN * Hh];
__device__ __align__(16) float g_emb[PP * NN * F];
__device__ __align__(16) float g_t1 [NN * F1];
__device__ __align__(16) float g_sc [NN * PP];
__device__ __align__(16) float g_z  [NN * F];
__device__ __align__(16) float g_t2 [NN * F1];

// ---------------- generic fp32 GEMM: C = act(A[MxK] @ B[KxN] + bias) -------
// 128x128 block tile, 256 threads, 8x8 microtile, 16-wide K tiles.
__global__ __launch_bounds__(256)
void gemm_kernel(const float* __restrict__ A, const float* __restrict__ B,
                 const float* __restrict__ bias, float* __restrict__ C,
                 int M, int K, int Nc, int act)
{
    __shared__ float As[16][128];   // [k][row]
    __shared__ float Bs[16][128];   // [k][col]

    const int tid = threadIdx.x;
    const int tx  = tid & 15;       // col group
    const int ty  = tid >> 4;       // row group
    const int row0 = blockIdx.y * 128 + ty * 8;
    const int col0 = blockIdx.x * 128 + tx * 8;

    float acc[8][8];
#pragma unroll
    for (int i = 0; i < 8; i++)
#pragma unroll
        for (int j = 0; j < 8; j++) acc[i][j] = 0.f;

    const int ar = tid >> 1;         // 0..127 : A row within tile
    const int ac = (tid & 1) * 8;    // 0 or 8 : A col within k-tile
    const int br = tid >> 4;         // 0..15  : B row within k-tile
    const int bc = (tid & 15) * 8;   // 0..120 : B col within tile

    for (int k0 = 0; k0 < K; k0 += 16) {
        // load A tile (transpose into [k][row])
        {
            int gr = blockIdx.y * 128 + ar;
            float4 a0, a1;
            if (gr < M) {
                const float* ap = A + (size_t)gr * K + k0 + ac;
                a0 = *(const float4*)(ap);
                a1 = *(const float4*)(ap + 4);
            } else {
                a0 = make_float4(0.f, 0.f, 0.f, 0.f);
                a1 = a0;
            }
            As[ac + 0][ar] = a0.x; As[ac + 1][ar] = a0.y;
            As[ac + 2][ar] = a0.z; As[ac + 3][ar] = a0.w;
            As[ac + 4][ar] = a1.x; As[ac + 5][ar] = a1.y;
            As[ac + 6][ar] = a1.z; As[ac + 7][ar] = a1.w;
        }
        // load B tile
        {
            const float* bp = B + (size_t)(k0 + br) * Nc + blockIdx.x * 128 + bc;
            *(float4*)&Bs[br][bc]     = *(const float4*)(bp);
            *(float4*)&Bs[br][bc + 4] = *(const float4*)(bp + 4);
        }
        __syncthreads();
#pragma unroll
        for (int kk = 0; kk < 16; kk++) {
            float a[8], b[8];
            *(float4*)(a)     = *(float4*)&As[kk][ty * 8];
            *(float4*)(a + 4) = *(float4*)&As[kk][ty * 8 + 4];
            *(float4*)(b)     = *(float4*)&Bs[kk][tx * 8];
            *(float4*)(b + 4) = *(float4*)&Bs[kk][tx * 8 + 4];
#pragma unroll
            for (int i = 0; i < 8; i++)
#pragma unroll
                for (int j = 0; j < 8; j++) acc[i][j] = fmaf(a[i], b[j], acc[i][j]);
        }
        __syncthreads();
    }

    float bv[8];
#pragma unroll
    for (int j = 0; j < 8; j++) bv[j] = bias ? bias[col0 + j] : 0.f;

#pragma unroll
    for (int i = 0; i < 8; i++) {
        int r = row0 + i;
        if (r >= M) break;
        float* cp = C + (size_t)r * Nc + col0;
#pragma unroll
        for (int j = 0; j < 8; j++) {
            float v = acc[i][j] + bv[j];
            if (act == 1)      v = tanhf(v);
            else if (act == 2) v = fmaxf(v, 0.f);
            cp[j] = v;
        }
    }
}

// ---------------- GAT attention prep: s_src, s_dst, m-init (self loop) -----
__global__ __launch_bounds__(256)
void attn_prep_kernel(const float* __restrict__ asrc, const float* __restrict__ adst)
{
    int n    = (blockIdx.x * 256 + threadIdx.x) >> 5;
    int lane = threadIdx.x & 31;
    if (n >= NN) return;
    const float* hp = g_hp + (size_t)n * F;
    float ss[8], sd[8];
#pragma unroll
    for (int k = 0; k < 8; k++) {
        int idx = k * 32 + lane;        // head k, dim lane
        float v = hp[idx];
        ss[k] = v * asrc[idx];
        sd[k] = v * adst[idx];
    }
#pragma unroll
    for (int k = 0; k < 8; k++) {
#pragma unroll
        for (int o = 16; o > 0; o >>= 1) {
            ss[k] += __shfl_xor_sync(0xFFFFFFFFu, ss[k], o);
            sd[k] += __shfl_xor_sync(0xFFFFFFFFu, sd[k], o);
        }
    }
    if (lane == 0) {
#pragma unroll
        for (int k = 0; k < 8; k++) {
            g_ssrc[n * 8 + k] = ss[k];
            g_sdst[n * 8 + k] = sd[k];
            float e = ss[k] + sd[k];           // self-loop logit
            e = (e > 0.f) ? e : 0.2f * e;      // leaky_relu(0.2)
            g_m[n * 8 + k] = e;                // max init (self loop always present)
        }
    }
}

__device__ __forceinline__ void atomicMaxF(float* addr, float v)
{
    if (v >= 0.f) atomicMax((int*)addr, __float_as_int(v));
    else          atomicMin((unsigned int*)addr, __float_as_uint(v));
}

// ---------------- edge pass 1: segment max over dst ------------------------
__global__ __launch_bounds__(256)
void edge_max_kernel(const int* __restrict__ src, const int* __restrict__ dst)
{
    int e = blockIdx.x * 256 + threadIdx.x;
    if (e >= EE) return;
    int s = src[e], d = dst[e];
    float4 s0 = *(const float4*)(g_ssrc + s * 8);
    float4 s1 = *(const float4*)(g_ssrc + s * 8 + 4);
    float4 d0 = *(const float4*)(g_sdst + d * 8);
    float4 d1 = *(const float4*)(g_sdst + d * 8 + 4);
    float ev[8] = {s0.x + d0.x, s0.y + d0.y, s0.z + d0.z, s0.w + d0.w,
                   s1.x + d1.x, s1.y + d1.y, s1.z + d1.z, s1.w + d1.w};
#pragma unroll
    for (int h = 0; h < 8; h++) {
        float v = ev[h];
        v = (v > 0.f) ? v : 0.2f * v;
        atomicMaxF(&g_m[d * 8 + h], v);
    }
}

// ---------------- edge pass 2: exp-weighted scatter accumulate -------------
__global__ __launch_bounds__(256)
void edge_acc_kernel(const int* __restrict__ src, const int* __restrict__ dst)
{
    int w    = (blockIdx.x * 256 + threadIdx.x) >> 5;  // one warp per edge
    int lane = threadIdx.x & 31;
    if (w >= EE) return;
    int s = src[w], d = dst[w];
    float ex = 0.f;
    if (lane < 8) {
        float v = g_ssrc[s * 8 + lane] + g_sdst[d * 8 + lane];
        v  = (v > 0.f) ? v : 0.2f * v;
        ex = __expf(v - g_m[d * 8 + lane]);
        atomicAdd(&g_den[d * 8 + lane], ex);
    }
    float exh[8];
#pragma unroll
    for (int k = 0; k < 8; k++) exh[k] = __shfl_sync(0xFFFFFFFFu, ex, k);
    const float* hp = g_hp  + (size_t)s * F;
    float*       ac = g_acc + (size_t)d * F;
#pragma unroll
    for (int k = 0; k < 8; k++) {
        int idx = k * 32 + lane;
        atomicAdd(&ac[idx], exh[k] * hp[idx]);
    }
}

// ---------------- finalize: self loop + normalize + bias + ELU -------------
__global__ __launch_bounds__(256)
void finalize_kernel(const float* __restrict__ bias, float* __restrict__ out)
{
    int n    = (blockIdx.x * 256 + threadIdx.x) >> 5;
    int lane = threadIdx.x & 31;
    if (n >= NN) return;
    float exs = 0.f, dtot = 1.f;
    if (lane < 8) {
        float e = g_ssrc[n * 8 + lane] + g_sdst[n * 8 + lane];
        e    = (e > 0.f) ? e : 0.2f * e;
        exs  = __expf(e - g_m[n * 8 + lane]);
        dtot = g_den[n * 8 + lane] + exs;
    }
    float exh[8], dh[8];
#pragma unroll
    for (int k = 0; k < 8; k++) {
        exh[k] = __shfl_sync(0xFFFFFFFFu, exs, k);
        dh[k]  = __shfl_sync(0xFFFFFFFFu, dtot, k);
    }
    const float* hp = g_hp  + (size_t)n * F;
    const float* ac = g_acc + (size_t)n * F;
    float*       op = out   + (size_t)n * F;
#pragma unroll
    for (int k = 0; k < 8; k++) {
        int idx = k * 32 + lane;
        float v = (ac[idx] + exh[k] * hp[idx]) / dh[k] + bias[idx];
        v = (v > 0.f) ? v : expm1f(v);       // ELU(alpha=1)
        op[idx] = v;
    }
}

// ---------------- semantic score: sc[n,p] = t1[n,:] . W2 -------------------
__global__ __launch_bounds__(256)
void sem_score_kernel(const float* __restrict__ W2, int p)
{
    int n    = (blockIdx.x * 256 + threadIdx.x) >> 5;
    int lane = threadIdx.x & 31;
    if (n >= NN) return;
    float ssum = 0.f;
#pragma unroll
    for (int k = 0; k < 4; k++) {
        int idx = k * 32 + lane;
        ssum = fmaf(g_t1[n * F1 + idx], W2[idx], ssum);
    }
#pragma unroll
    for (int o = 16; o > 0; o >>= 1) ssum += __shfl_xor_sync(0xFFFFFFFFu, ssum, o);
    if (lane == 0) g_sc[n * PP + p] = ssum;
}

// ---------------- semantic softmax + weighted combine ----------------------
__global__ __launch_bounds__(256)
void sem_combine_kernel()
{
    int n    = (blockIdx.x * 256 + threadIdx.x) >> 5;
    int lane = threadIdx.x & 31;
    if (n >= NN) return;
    float s0 = g_sc[n * PP + 0], s1 = g_sc[n * PP + 1], s2 = g_sc[n * PP + 2];
    float mx = fmaxf(s0, fmaxf(s1, s2));
    float w0 = __expf(s0 - mx), w1 = __expf(s1 - mx), w2 = __expf(s2 - mx);
    float inv = 1.f / (w0 + w1 + w2);
    w0 *= inv; w1 *= inv; w2 *= inv;
    const float* e0 = g_emb + (size_t)n * F;
    const float* e1 = g_emb + (size_t)(NN + n) * F;
    const float* e2 = g_emb + (size_t)(2 * NN + n) * F;
    float* zp = g_z + (size_t)n * F;
#pragma unroll
    for (int k = 0; k < 8; k++) {
        int idx = k * 32 + lane;
        zp[idx] = w0 * e0[idx] + w1 * e1[idx] + w2 * e2[idx];
    }
}

// ---------------- classifier head: logits = t2 @ W2 + b2 -------------------
__global__ __launch_bounds__(256)
void cls_out_kernel(const float* __restrict__ W2, const float* __restrict__ b2,
                    float* __restrict__ out)
{
    int n    = (blockIdx.x * 256 + threadIdx.x) >> 5;
    int lane = threadIdx.x & 31;
    if (n >= NN) return;
    float c0 = 0.f, c1 = 0.f;
#pragma unroll
    for (int k = 0; k < 4; k++) {
        int idx = k * 32 + lane;
        float t = g_t2[n * F1 + idx];
        c0 = fmaf(t, W2[idx * 2 + 0], c0);
        c1 = fmaf(t, W2[idx * 2 + 1], c1);
    }
#pragma unroll
    for (int o = 16; o > 0; o >>= 1) {
        c0 += __shfl_xor_sync(0xFFFFFFFFu, c0, o);
        c1 += __shfl_xor_sync(0xFFFFFFFFu, c1, o);
    }
    if (lane == 0) {
        out[n * 2 + 0] = c0 + b2[0];
        out[n * 2 + 1] = c1 + b2[1];
    }
}

// ---------------- driver ---------------------------------------------------
extern "C" void kernel_launch(void* const* d_in, const int* in_sizes, int n_in,
                              void* d_out, int out_size)
{
    const float* x        = (const float*)d_in[0];
    const int*   edges    = (const int*)  d_in[1];
    const float* proj_W   = (const float*)d_in[2];
    const float* proj_b   = (const float*)d_in[3];
    const float* gat_W    = (const float*)d_in[4];
    const float* gat_asrc = (const float*)d_in[5];
    const float* gat_adst = (const float*)d_in[6];
    const float* gat_b    = (const float*)d_in[7];
    const float* sem_W1   = (const float*)d_in[8];
    const float* sem_b1   = (const float*)d_in[9];
    const float* sem_W2   = (const float*)d_in[10];
    const float* cls_W1   = (const float*)d_in[11];
    const float* cls_b1   = (const float*)d_in[12];
    const float* cls_W2   = (const float*)d_in[13];
    const float* cls_b2   = (const float*)d_in[14];
    float* out = (float*)d_out;

    float *h0, *h, *hp, *acc, *den, *emb, *t1, *t2, *z;
    cudaGetSymbolAddress((void**)&h0,  g_h0);
    cudaGetSymbolAddress((void**)&h,   g_h);
    cudaGetSymbolAddress((void**)&hp,  g_hp);
    cudaGetSymbolAddress((void**)&acc, g_acc);
    cudaGetSymbolAddress((void**)&den, g_den);
    cudaGetSymbolAddress((void**)&emb, g_emb);
    cudaGetSymbolAddress((void**)&t1,  g_t1);
    cudaGetSymbolAddress((void**)&t2,  g_t2);
    cudaGetSymbolAddress((void**)&z,   g_z);

    const int MB = (NN + 127) / 128;          // 391 row tiles
    const int nodeWarpBlocks = (NN + 7) / 8;  // warp-per-node kernels
    const int edgeBlocks     = (EE + 255) / 256;
    const int edgeWarpBlocks = (EE + 7) / 8;

    // h0 = x @ proj_W + proj_b
    gemm_kernel<<<dim3(2, MB), 256>>>(x, proj_W, proj_b, h0, NN, 128, F, 0);

    for (int p = 0; p < PP; p++) {
        const int* src0 = edges + (size_t)p * 2 * EE;
        const int* dst0 = src0 + EE;
        const float* hin = h0;
        for (int l = 0; l < 2; l++) {
            int li = p * 2 + l;
            const float* W  = gat_W    + (size_t)li * F * F;
            const float* as = gat_asrc + (size_t)li * Hh * DHd;
            const float* ad = gat_adst + (size_t)li * Hh * DHd;
            const float* bb = gat_b    + (size_t)li * F;

            gemm_kernel<<<dim3(2, MB), 256>>>(hin, W, nullptr, hp, NN, F, F, 0);
            cudaMemsetAsync(acc, 0, sizeof(float) * NN * F);
            cudaMemsetAsync(den, 0, sizeof(float) * NN * Hh);
            attn_prep_kernel<<<nodeWarpBlocks, 256>>>(as, ad);
            edge_max_kernel<<<edgeBlocks, 256>>>(src0, dst0);
            edge_acc_kernel<<<edgeWarpBlocks, 256>>>(src0, dst0);
            float* obuf = (l == 0) ? h : (emb + (size_t)p * NN * F);
            finalize_kernel<<<nodeWarpBlocks, 256>>>(bb, obuf);
            hin = h;
        }
    }

    // semantic attention
    for (int p = 0; p < PP; p++) {
        gemm_kernel<<<dim3(1, MB), 256>>>(emb + (size_t)p * NN * F, sem_W1, sem_b1,
                                          t1, NN, F, F1, 1);
        sem_score_kernel<<<nodeWarpBlocks, 256>>>(sem_W2, p);
    }
    sem_combine_kernel<<<nodeWarpBlocks, 256>>>();

    // classifier
    gemm_kernel<<<dim3(1, MB), 256>>>(z, cls_W1, cls_b1, t2, NN, F, F1, 2);
    cls_out_kernel<<<nodeWarpBlocks, 256>>>(cls_W2, cls_b2, out);
}

// round 6
// speedup vs baseline: 1.5651x; 1.5651x over previous
#include <cuda_runtime.h>
#include <cuda_bf16.h>
#include <math.h>

// Problem constants (fixed by the dataset)
constexpr int NN  = 50000;   // nodes
constexpr int F   = 256;     // hidden
constexpr int Hh  = 8;       // heads
constexpr int DHd = 32;      // per-head dim
constexpr int EE  = 800000;  // edges per metapath
constexpr int PP  = 3;       // metapaths
constexpr int F1  = 128;     // MLP hidden

// ---------------- scratch (device globals; no allocation allowed) ----------
__device__ __align__(16) float g_h0 [NN * F];
__device__ __align__(16) float g_h  [NN * F];
__device__ __align__(16) float g_hp [NN * F];
__device__ __align__(16) float g_ssrc[NN * Hh];
__device__ __align__(16) float g_sdst[NN * Hh];
__device__ __align__(16) float g_emb[PP * NN * F];
__device__ __align__(16) float g_t1 [NN * F1];
__device__ __align__(16) float g_sc [NN * PP];
__device__ __align__(16) float g_z  [NN * F];
__device__ __align__(16) float g_t2 [NN * F1];

// CSR structures (built once per call; edges fixed per metapath)
__device__ int g_count [PP * NN];
__device__ int g_indptr[PP * (NN + 1)];
__device__ int g_cursor[PP * NN];
__device__ int g_csrc  [PP * EE];

// ---------------- generic fp32 GEMM: C = act(A[MxK] @ B[KxN] + bias) -------
__global__ __launch_bounds__(256)
void gemm_kernel(const float* __restrict__ A, const float* __restrict__ B,
                 const float* __restrict__ bias, float* __restrict__ C,
                 int M, int K, int Nc, int act)
{
    __shared__ float As[16][128];   // [k][row]
    __shared__ float Bs[16][128];   // [k][col]

    const int tid = threadIdx.x;
    const int tx  = tid & 15;       // col group
    const int ty  = tid >> 4;       // row group
    const int row0 = blockIdx.y * 128 + ty * 8;
    const int col0 = blockIdx.x * 128 + tx * 8;

    float acc[8][8];
#pragma unroll
    for (int i = 0; i < 8; i++)
#pragma unroll
        for (int j = 0; j < 8; j++) acc[i][j] = 0.f;

    const int ar = tid >> 1;         // 0..127 : A row within tile
    const int ac = (tid & 1) * 8;    // 0 or 8 : A col within k-tile
    const int br = tid >> 4;         // 0..15  : B row within k-tile
    const int bc = (tid & 15) * 8;   // 0..120 : B col within tile

    for (int k0 = 0; k0 < K; k0 += 16) {
        {
            int gr = blockIdx.y * 128 + ar;
            float4 a0, a1;
            if (gr < M) {
                const float* ap = A + (size_t)gr * K + k0 + ac;
                a0 = *(const float4*)(ap);
                a1 = *(const float4*)(ap + 4);
            } else {
                a0 = make_float4(0.f, 0.f, 0.f, 0.f);
                a1 = a0;
            }
            As[ac + 0][ar] = a0.x; As[ac + 1][ar] = a0.y;
            As[ac + 2][ar] = a0.z; As[ac + 3][ar] = a0.w;
            As[ac + 4][ar] = a1.x; As[ac + 5][ar] = a1.y;
            As[ac + 6][ar] = a1.z; As[ac + 7][ar] = a1.w;
        }
        {
            const float* bp = B + (size_t)(k0 + br) * Nc + blockIdx.x * 128 + bc;
            *(float4*)&Bs[br][bc]     = *(const float4*)(bp);
            *(float4*)&Bs[br][bc + 4] = *(const float4*)(bp + 4);
        }
        __syncthreads();
#pragma unroll
        for (int kk = 0; kk < 16; kk++) {
            float a[8], b[8];
            *(float4*)(a)     = *(float4*)&As[kk][ty * 8];
            *(float4*)(a + 4) = *(float4*)&As[kk][ty * 8 + 4];
            *(float4*)(b)     = *(float4*)&Bs[kk][tx * 8];
            *(float4*)(b + 4) = *(float4*)&Bs[kk][tx * 8 + 4];
#pragma unroll
            for (int i = 0; i < 8; i++)
#pragma unroll
                for (int j = 0; j < 8; j++) acc[i][j] = fmaf(a[i], b[j], acc[i][j]);
        }
        __syncthreads();
    }

    float bv[8];
#pragma unroll
    for (int j = 0; j < 8; j++) bv[j] = bias ? bias[col0 + j] : 0.f;

#pragma unroll
    for (int i = 0; i < 8; i++) {
        int r = row0 + i;
        if (r >= M) break;
        float* cp = C + (size_t)r * Nc + col0;
#pragma unroll
        for (int j = 0; j < 8; j++) {
            float v = acc[i][j] + bv[j];
            if (act == 1)      v = tanhf(v);
            else if (act == 2) v = fmaxf(v, 0.f);
            cp[j] = v;
        }
    }
}

// ---------------- CSR build ------------------------------------------------
__global__ __launch_bounds__(256)
void csr_count_kernel(const int* __restrict__ edges)
{
    int idx = blockIdx.x * 256 + threadIdx.x;
    if (idx >= PP * EE) return;
    int p = idx / EE, e = idx - p * EE;
    int d = edges[(size_t)p * 2 * EE + EE + e];
    atomicAdd(&g_count[p * NN + d], 1);
}

// single-block chunked exclusive scan for all metapaths
__global__ __launch_bounds__(1024)
void csr_scan_kernel()
{
    __shared__ int warp_off[32];
    __shared__ int s_carry;
    const int lane = threadIdx.x & 31;
    const int wid  = threadIdx.x >> 5;

    for (int p = 0; p < PP; p++) {
        const int* counts = g_count  + p * NN;
        int*       indptr = g_indptr + p * (NN + 1);
        int*       cursor = g_cursor + p * NN;
        if (threadIdx.x == 0) s_carry = 0;
        __syncthreads();
        for (int base = 0; base < NN; base += 1024) {
            int i = base + (int)threadIdx.x;
            int v = (i < NN) ? counts[i] : 0;
            int incl = v;
#pragma unroll
            for (int o = 1; o < 32; o <<= 1) {
                int t = __shfl_up_sync(0xFFFFFFFFu, incl, o);
                if (lane >= o) incl += t;
            }
            if (lane == 31) warp_off[wid] = incl;
            __syncthreads();
            if (wid == 0) {
                int ws = warp_off[lane];
                int wincl = ws;
#pragma unroll
                for (int o = 1; o < 32; o <<= 1) {
                    int t = __shfl_up_sync(0xFFFFFFFFu, wincl, o);
                    if (lane >= o) wincl += t;
                }
                warp_off[lane] = wincl - ws;   // exclusive warp offsets
            }
            __syncthreads();
            int excl = incl - v + warp_off[wid] + s_carry;
            if (i < NN) { indptr[i] = excl; cursor[i] = excl; }
            __syncthreads();
            if (threadIdx.x == 1023) s_carry = excl + v;
            __syncthreads();
        }
        if (threadIdx.x == 0) indptr[NN] = s_carry;
        __syncthreads();
    }
}

__global__ __launch_bounds__(256)
void csr_scatter_kernel(const int* __restrict__ edges)
{
    int idx = blockIdx.x * 256 + threadIdx.x;
    if (idx >= PP * EE) return;
    int p = idx / EE, e = idx - p * EE;
    int s = edges[(size_t)p * 2 * EE + e];
    int d = edges[(size_t)p * 2 * EE + EE + e];
    int pos = atomicAdd(&g_cursor[p * NN + d], 1);
    g_csrc[(size_t)p * EE + pos] = s;
}

// ---------------- GAT attention prep: s_src, s_dst -------------------------
__global__ __launch_bounds__(256)
void attn_prep_kernel(const float* __restrict__ asrc, const float* __restrict__ adst)
{
    int n    = (blockIdx.x * 256 + threadIdx.x) >> 5;
    int lane = threadIdx.x & 31;
    if (n >= NN) return;
    const float* hp = g_hp + (size_t)n * F;
    float ss[8], sd[8];
#pragma unroll
    for (int k = 0; k < 8; k++) {
        int idx = k * 32 + lane;
        float v = hp[idx];
        ss[k] = v * asrc[idx];
        sd[k] = v * adst[idx];
    }
#pragma unroll
    for (int k = 0; k < 8; k++) {
#pragma unroll
        for (int o = 16; o > 0; o >>= 1) {
            ss[k] += __shfl_xor_sync(0xFFFFFFFFu, ss[k], o);
            sd[k] += __shfl_xor_sync(0xFFFFFFFFu, sd[k], o);
        }
    }
    if (lane == 0) {
#pragma unroll
        for (int k = 0; k < 8; k++) {
            g_ssrc[n * 8 + k] = ss[k];
            g_sdst[n * 8 + k] = sd[k];
        }
    }
}

__device__ __forceinline__ float leaky02(float v) { return (v > 0.f) ? v : 0.2f * v; }

// ---------------- fused CSR aggregate: max/exp/denom/gather/ELU ------------
// one warp per dst node, accumulators fully in registers, no atomics
__global__ __launch_bounds__(256)
void gat_aggregate_kernel(const int* __restrict__ indptr, const int* __restrict__ csrc,
                          const float* __restrict__ bias, float* __restrict__ out)
{
    int n    = (blockIdx.x * 256 + threadIdx.x) >> 5;
    int lane = threadIdx.x & 31;
    if (n >= NN) return;

    const int beg = indptr[n];
    const int end = indptr[n + 1];

    // lanes 0..7 hold per-head scalars
    float sd = 0.f, eself = 0.f;
    if (lane < 8) {
        sd    = g_sdst[n * 8 + lane];
        eself = leaky02(g_ssrc[n * 8 + lane] + sd);
    }
    // pass 1: per-head max over incoming edges (self loop included)
    float m = eself;
    for (int ptr = beg; ptr < end; ptr++) {
        int s = csrc[ptr];
        if (lane < 8)
            m = fmaxf(m, leaky02(g_ssrc[s * 8 + lane] + sd));
    }

    // pass 2: exp-weighted gather accumulate
    float den = (lane < 8) ? __expf(eself - m) : 0.f;  // self loop contribution
    const float exself = den;
    float accv[8];
#pragma unroll
    for (int k = 0; k < 8; k++) accv[k] = 0.f;

    for (int ptr = beg; ptr < end; ptr++) {
        int s = csrc[ptr];
        float ex = 0.f;
        if (lane < 8) {
            ex = __expf(leaky02(g_ssrc[s * 8 + lane] + sd) - m);
            den += ex;
        }
        float exh[8];
#pragma unroll
        for (int k = 0; k < 8; k++) exh[k] = __shfl_sync(0xFFFFFFFFu, ex, k);
        const float* hp = g_hp + (size_t)s * F;
#pragma unroll
        for (int k = 0; k < 8; k++)
            accv[k] = fmaf(exh[k], hp[k * 32 + lane], accv[k]);
    }

    // finalize: self hp contribution, normalize, bias, ELU
    float exsh[8], dh[8];
#pragma unroll
    for (int k = 0; k < 8; k++) {
        exsh[k] = __shfl_sync(0xFFFFFFFFu, exself, k);
        dh[k]   = __shfl_sync(0xFFFFFFFFu, den, k);
    }
    const float* hpn = g_hp + (size_t)n * F;
    float*       op  = out  + (size_t)n * F;
#pragma unroll
    for (int k = 0; k < 8; k++) {
        int idx = k * 32 + lane;
        float v = (accv[k] + exsh[k] * hpn[idx]) / dh[k] + bias[idx];
        v = (v > 0.f) ? v : expm1f(v);   // ELU(alpha=1)
        op[idx] = v;
    }
}

// ---------------- semantic score: sc[n,p] = t1[n,:] . W2 -------------------
__global__ __launch_bounds__(256)
void sem_score_kernel(const float* __restrict__ W2, int p)
{
    int n    = (blockIdx.x * 256 + threadIdx.x) >> 5;
    int lane = threadIdx.x & 31;
    if (n >= NN) return;
    float ssum = 0.f;
#pragma unroll
    for (int k = 0; k < 4; k++) {
        int idx = k * 32 + lane;
        ssum = fmaf(g_t1[n * F1 + idx], W2[idx], ssum);
    }
#pragma unroll
    for (int o = 16; o > 0; o >>= 1) ssum += __shfl_xor_sync(0xFFFFFFFFu, ssum, o);
    if (lane == 0) g_sc[n * PP + p] = ssum;
}

// ---------------- semantic softmax + weighted combine ----------------------
__global__ __launch_bounds__(256)
void sem_combine_kernel()
{
    int n    = (blockIdx.x * 256 + threadIdx.x) >> 5;
    int lane = threadIdx.x & 31;
    if (n >= NN) return;
    float s0 = g_sc[n * PP + 0], s1 = g_sc[n * PP + 1], s2 = g_sc[n * PP + 2];
    float mx = fmaxf(s0, fmaxf(s1, s2));
    float w0 = __expf(s0 - mx), w1 = __expf(s1 - mx), w2 = __expf(s2 - mx);
    float inv = 1.f / (w0 + w1 + w2);
    w0 *= inv; w1 *= inv; w2 *= inv;
    const float* e0 = g_emb + (size_t)n * F;
    const float* e1 = g_emb + (size_t)(NN + n) * F;
    const float* e2 = g_emb + (size_t)(2 * NN + n) * F;
    float* zp = g_z + (size_t)n * F;
#pragma unroll
    for (int k = 0; k < 8; k++) {
        int idx = k * 32 + lane;
        zp[idx] = w0 * e0[idx] + w1 * e1[idx] + w2 * e2[idx];
    }
}

// ---------------- classifier head: logits = t2 @ W2 + b2 -------------------
__global__ __launch_bounds__(256)
void cls_out_kernel(const float* __restrict__ W2, const float* __restrict__ b2,
                    float* __restrict__ out)
{
    int n    = (blockIdx.x * 256 + threadIdx.x) >> 5;
    int lane = threadIdx.x & 31;
    if (n >= NN) return;
    float c0 = 0.f, c1 = 0.f;
#pragma unroll
    for (int k = 0; k < 4; k++) {
        int idx = k * 32 + lane;
        float t = g_t2[n * F1 + idx];
        c0 = fmaf(t, W2[idx * 2 + 0], c0);
        c1 = fmaf(t, W2[idx * 2 + 1], c1);
    }
#pragma unroll
    for (int o = 16; o > 0; o >>= 1) {
        c0 += __shfl_xor_sync(0xFFFFFFFFu, c0, o);
        c1 += __shfl_xor_sync(0xFFFFFFFFu, c1, o);
    }
    if (lane == 0) {
        out[n * 2 + 0] = c0 + b2[0];
        out[n * 2 + 1] = c1 + b2[1];
    }
}

// ---------------- driver ---------------------------------------------------
extern "C" void kernel_launch(void* const* d_in, const int* in_sizes, int n_in,
                              void* d_out, int out_size)
{
    const float* x        = (const float*)d_in[0];
    const int*   edges    = (const int*)  d_in[1];
    const float* proj_W   = (const float*)d_in[2];
    const float* proj_b   = (const float*)d_in[3];
    const float* gat_W    = (const float*)d_in[4];
    const float* gat_asrc = (const float*)d_in[5];
    const float* gat_adst = (const float*)d_in[6];
    const float* gat_b    = (const float*)d_in[7];
    const float* sem_W1   = (const float*)d_in[8];
    const float* sem_b1   = (const float*)d_in[9];
    const float* sem_W2   = (const float*)d_in[10];
    const float* cls_W1   = (const float*)d_in[11];
    const float* cls_b1   = (const float*)d_in[12];
    const float* cls_W2   = (const float*)d_in[13];
    const float* cls_b2   = (const float*)d_in[14];
    float* out = (float*)d_out;

    float *h0, *h, *hp, *emb, *t1, *t2, *z;
    int *countp, *indptr, *csrc;
    cudaGetSymbolAddress((void**)&h0,  g_h0);
    cudaGetSymbolAddress((void**)&h,   g_h);
    cudaGetSymbolAddress((void**)&hp,  g_hp);
    cudaGetSymbolAddress((void**)&emb, g_emb);
    cudaGetSymbolAddress((void**)&t1,  g_t1);
    cudaGetSymbolAddress((void**)&t2,  g_t2);
    cudaGetSymbolAddress((void**)&z,   g_z);
    cudaGetSymbolAddress((void**)&countp, g_count);
    cudaGetSymbolAddress((void**)&indptr, g_indptr);
    cudaGetSymbolAddress((void**)&csrc,   g_csrc);

    const int MB = (NN + 127) / 128;          // row tiles
    const int nodeWarpBlocks = (NN + 7) / 8;  // warp-per-node kernels
    const int allEdgeBlocks  = (PP * EE + 255) / 256;

    // --- CSR build for all metapaths (edges are inputs; rebuilt every call) ---
    cudaMemsetAsync(countp, 0, sizeof(int) * PP * NN);
    csr_count_kernel<<<allEdgeBlocks, 256>>>(edges);
    csr_scan_kernel<<<1, 1024>>>();
    csr_scatter_kernel<<<allEdgeBlocks, 256>>>(edges);

    // h0 = x @ proj_W + proj_b
    gemm_kernel<<<dim3(2, MB), 256>>>(x, proj_W, proj_b, h0, NN, 128, F, 0);

    for (int p = 0; p < PP; p++) {
        const int* ip = indptr + (size_t)p * (NN + 1);
        const int* cs = csrc   + (size_t)p * EE;
        const float* hin = h0;
        for (int l = 0; l < 2; l++) {
            int li = p * 2 + l;
            const float* W  = gat_W    + (size_t)li * F * F;
            const float* as = gat_asrc + (size_t)li * Hh * DHd;
            const float* ad = gat_adst + (size_t)li * Hh * DHd;
            const float* bb = gat_b    + (size_t)li * F;

            gemm_kernel<<<dim3(2, MB), 256>>>(hin, W, nullptr, hp, NN, F, F, 0);
            attn_prep_kernel<<<nodeWarpBlocks, 256>>>(as, ad);
            float* obuf = (l == 0) ? h : (emb + (size_t)p * NN * F);
            gat_aggregate_kernel<<<nodeWarpBlocks, 256>>>(ip, cs, bb, obuf);
            hin = h;
        }
    }

    // semantic attention
    for (int p = 0; p < PP; p++) {
        gemm_kernel<<<dim3(1, MB), 256>>>(emb + (size_t)p * NN * F, sem_W1, sem_b1,
                                          t1, NN, F, F1, 1);
        sem_score_kernel<<<nodeWarpBlocks, 256>>>(sem_W2, p);
    }
    sem_combine_kernel<<<nodeWarpBlocks, 256>>>();

    // classifier
    gemm_kernel<<<dim3(1, MB), 256>>>(z, cls_W1, cls_b1, t2, NN, F, F1, 2);
    cls_out_kernel<<<nodeWarpBlocks, 256>>>(cls_W2, cls_b2, out);
}

// round 12
// speedup vs baseline: 2.4081x; 1.5386x over previous
#include <cuda_runtime.h>
#include <cuda_bf16.h>
#include <math.h>
#include <stdint.h>
#include <string.h>

// Problem constants (fixed by the dataset)
constexpr int NN  = 50000;   // nodes
constexpr int F   = 256;     // hidden
constexpr int Hh  = 8;       // heads
constexpr int DHd = 32;      // per-head dim
constexpr int EE  = 800000;  // edges per metapath
constexpr int PP  = 3;       // metapaths
constexpr int F1  = 128;     // MLP hidden

// ---------------- scratch (device globals; no allocation allowed) ----------
__device__ __align__(16) float g_h0 [NN * F];
__device__ __align__(16) float g_h  [NN * F];
__device__ __align__(16) float g_hp [NN * F];
__device__ __align__(16) float g_ssrc[NN * Hh];
__device__ __align__(16) float g_sdst[NN * Hh];
__device__ __align__(16) float g_emb[PP * NN * F];
__device__ __align__(16) float g_t1 [NN * F1];
__device__ __align__(16) float g_sc [NN * PP];
__device__ __align__(16) float g_z  [NN * F];
__device__ __align__(16) float g_t2 [NN * F1];

// CSR structures
__device__ int g_count [PP * NN];
__device__ int g_indptr[PP * (NN + 1)];
__device__ int g_cursor[PP * NN];
__device__ int g_csrc  [PP * EE];

// split-bf16 weights, transposed to [N][K], hi then lo per matrix
__device__ __align__(16) __nv_bfloat16 g_wt[983040];

// feature gate: tcgen05 only exists in an arch-specific (sm_103a/100a) pass
#if defined(__CUDA_ARCH_FEAT_SM103_ALL) || defined(__CUDA_ARCH_FEAT_SM100_ALL) || defined(__CUDA_ARCH_FEAT_SM101_ALL)
#define HAVE_TCGEN05 1
#else
#define HAVE_TCGEN05 0
#endif

// ---------------- PTX helpers (used only under HAVE_TCGEN05) ---------------
__device__ __forceinline__ uint32_t elect_one_pred() {
    uint32_t pred;
    asm volatile(
        "{\n\t.reg .pred p;\n\t"
        "elect.sync _|p, 0xFFFFFFFF;\n\t"
        "selp.b32 %0, 1, 0, p;\n\t}"
        : "=r"(pred));
    return pred;
}
__device__ __forceinline__ uint32_t smem_u32(const void* p) {
    uint32_t a;
    asm("{ .reg .u64 t; cvta.to.shared.u64 t, %1; cvt.u32.u64 %0, t; }"
        : "=r"(a) : "l"(p));
    return a;
}

static constexpr uint64_t SMEM_DESC_BASE_SW128 =
    (uint64_t(2)  << 61) | (uint64_t(1) << 46) | (uint64_t(64) << 32) | (uint64_t(1) << 16);

__device__ __forceinline__ uint64_t make_desc(uint32_t addr) {
    return SMEM_DESC_BASE_SW128 | ((uint64_t)(addr >> 4) & 0x3FFF);
}

#if HAVE_TCGEN05
__device__ __forceinline__ void tc_alloc(uint32_t smem_dst, uint32_t ncols) {
    asm volatile("tcgen05.alloc.cta_group::1.sync.aligned.shared::cta.b32 [%0], %1;"
                 :: "r"(smem_dst), "r"(ncols) : "memory");
}
__device__ __forceinline__ void tc_relinquish() {
    asm volatile("tcgen05.relinquish_alloc_permit.cta_group::1.sync.aligned;");
}
__device__ __forceinline__ void tc_dealloc(uint32_t tmem, uint32_t ncols) {
    asm volatile("tcgen05.dealloc.cta_group::1.sync.aligned.b32 %0, %1;"
                 :: "r"(tmem), "r"(ncols));
}
__device__ __forceinline__ void mbar_init(uint32_t mbar, uint32_t cnt) {
    asm volatile("mbarrier.init.shared.b64 [%0], %1;" :: "r"(mbar), "r"(cnt) : "memory");
}
__device__ __forceinline__ void mbar_inval(uint32_t mbar) {
    asm volatile("mbarrier.inval.shared.b64 [%0];" :: "r"(mbar) : "memory");
}
__device__ __forceinline__ void mbar_wait(uint32_t mbar, uint32_t parity) {
    asm volatile(
        "{\n\t.reg .pred P;\n"
        "W_%=:\n\t"
        "mbarrier.try_wait.parity.acquire.cta.shared::cta.b64 P, [%0], %1, 0x989680;\n\t"
        "@P bra.uni D_%=;\n\t"
        "bra.uni W_%=;\n"
        "D_%=:\n\t}"
        :: "r"(mbar), "r"(parity) : "memory");
}
__device__ __forceinline__ void tc_commit(uint32_t mbar) {
    asm volatile("tcgen05.commit.cta_group::1.mbarrier::arrive::one.shared::cluster.b64 [%0];"
                 :: "r"(mbar) : "memory");
}
__device__ __forceinline__ void tc_mma_bf16_ss(uint32_t d, uint64_t ad, uint64_t bd,
                                               uint32_t idesc, uint32_t en) {
    asm volatile(
        "{\n\t.reg .pred p;\n\t"
        "setp.ne.u32 p, %5, 0;\n\t"
        "tcgen05.mma.cta_group::1.kind::f16 [%0], %1, %2, %3, {%4, %4, %4, %4}, p;\n\t}"
        :: "r"(d), "l"(ad), "l"(bd), "r"(idesc), "r"(0u), "r"(en)
        : "memory");
}
#define TC_LD_32X32B_X32(r, addr) \
    asm volatile( \
        "tcgen05.ld.sync.aligned.32x32b.x32.b32 " \
        "{%0, %1, %2, %3, %4, %5, %6, %7, " \
        " %8, %9, %10, %11, %12, %13, %14, %15, " \
        " %16, %17, %18, %19, %20, %21, %22, %23, " \
        " %24, %25, %26, %27, %28, %29, %30, %31}, [%32];" \
        : "=r"((r)[0]),  "=r"((r)[1]),  "=r"((r)[2]),  "=r"((r)[3]), \
          "=r"((r)[4]),  "=r"((r)[5]),  "=r"((r)[6]),  "=r"((r)[7]), \
          "=r"((r)[8]),  "=r"((r)[9]),  "=r"((r)[10]), "=r"((r)[11]), \
          "=r"((r)[12]), "=r"((r)[13]), "=r"((r)[14]), "=r"((r)[15]), \
          "=r"((r)[16]), "=r"((r)[17]), "=r"((r)[18]), "=r"((r)[19]), \
          "=r"((r)[20]), "=r"((r)[21]), "=r"((r)[22]), "=r"((r)[23]), \
          "=r"((r)[24]), "=r"((r)[25]), "=r"((r)[26]), "=r"((r)[27]), \
          "=r"((r)[28]), "=r"((r)[29]), "=r"((r)[30]), "=r"((r)[31]) \
        : "r"(addr))
#endif  // HAVE_TCGEN05

__device__ __forceinline__ uint32_t pack2(__nv_bfloat16 a, __nv_bfloat16 b) {
    __nv_bfloat162 t; t.x = a; t.y = b;
    uint32_t u; memcpy(&u, &t, 4); return u;
}

// ---------------- weight conversion: W[K][N] fp32 -> Wt_hi/lo [N][K] bf16 --
__global__ __launch_bounds__(256)
void conv_w_kernel(const float* __restrict__ src, __nv_bfloat16* __restrict__ hi,
                   __nv_bfloat16* __restrict__ lo, int K, int N)
{
    int idx = blockIdx.x * 256 + threadIdx.x;
    if (idx >= K * N) return;
    int k = idx / N, n = idx - k * N;
    float v = src[idx];
    __nv_bfloat16 h = __float2bfloat16(v);
    float l = v - __bfloat162float(h);
    hi[(size_t)n * K + k] = h;
    lo[(size_t)n * K + k] = __float2bfloat16(l);
}

// ---------------- GEMM: C[m0:m0+128, c0:c0+128] tile per block --------------
// C = act(A[M,K] @ W[K,N] + bias); W given split-bf16 transposed [N][K].
// act: 0 none, 1 tanh, 2 relu, 3 GAT (no bias; emit per-head ssrc/sdst).
// grid: (N/128, ceil(M/128)); 256 threads; dynamic smem 66560 B.
__global__ __launch_bounds__(256)
void gemm_tc(const float* __restrict__ A, const __nv_bfloat16* __restrict__ Bhi,
             const __nv_bfloat16* __restrict__ Blo, const float* __restrict__ bias,
             float* __restrict__ C, int M, int K, int N, int act,
             const float* __restrict__ asrc, const float* __restrict__ adst,
             float* __restrict__ ssrc, float* __restrict__ sdst)
{
    extern __shared__ char smem[];
    const int tid  = threadIdx.x;
    const int wid  = tid >> 5;
    const int lane = tid & 31;
    const int m0   = blockIdx.y * 128;
    const int c0   = blockIdx.x * 128;     // column-tile base (also n-base of Wt)

#if HAVE_TCGEN05
    // =================== tcgen05 split-bf16 path ===========================
    const uint32_t sb = smem_u32(smem);
    const int SM_AHI = 1024;
    const int SM_ALO = 1024 + 16384;
    const int SM_BHI = 1024 + 32768;
    const int SM_BLO = 1024 + 49152;

    if (wid == 0) { tc_alloc(sb, 128u); tc_relinquish(); }
    if (tid == 0) { mbar_init(sb + 8, 1); }
    __syncthreads();
    uint32_t tmem;
    asm volatile("ld.shared.b32 %0, [%1];" : "=r"(tmem) : "r"(sb));

    const uint32_t idesc = 0x490u | (16u << 17) | (8u << 24);  // bf16, M128, N128
    const int nchunks = K >> 6;

    for (int ch = 0; ch < nchunks; ch++) {
        const int k0 = ch << 6;
        // A tile: fp32 -> bf16 hi/lo, SW128 [128 rows x 64 k]
        {
            const int r  = tid >> 1;
            const int cb = (tid & 1) * 32;
            const int gr = m0 + r;
            const bool vr = gr < M;
            const float* ap = A + (size_t)gr * K + k0 + cb;
#pragma unroll
            for (int j = 0; j < 8; j++) {
                float4 v = vr ? *(const float4*)(ap + j * 4)
                              : make_float4(0.f, 0.f, 0.f, 0.f);
                __nv_bfloat16 hx = __float2bfloat16(v.x);
                __nv_bfloat16 hy = __float2bfloat16(v.y);
                __nv_bfloat16 hz = __float2bfloat16(v.z);
                __nv_bfloat16 hw = __float2bfloat16(v.w);
                __nv_bfloat16 lx = __float2bfloat16(v.x - __bfloat162float(hx));
                __nv_bfloat16 ly = __float2bfloat16(v.y - __bfloat162float(hy));
                __nv_bfloat16 lz = __float2bfloat16(v.z - __bfloat162float(hz));
                __nv_bfloat16 lw = __float2bfloat16(v.w - __bfloat162float(hw));
                uint32_t byte = (uint32_t)(r * 128 + (cb + j * 4) * 2);
                uint32_t sw   = byte ^ ((byte >> 3) & 0x70);
                *(uint2*)(smem + SM_AHI + sw) = make_uint2(pack2(hx, hy), pack2(hz, hw));
                *(uint2*)(smem + SM_ALO + sw) = make_uint2(pack2(lx, ly), pack2(lz, lw));
            }
        }
        // B tiles: 128 n-rows x 64 k bf16, SW128, from [N][K] gmem
        {
#pragma unroll
            for (int it = 0; it < 4; it++) {
                int idx = it * 256 + tid;
                int n  = idx >> 3;
                int kp = idx & 7;
                uint32_t byte = (uint32_t)(n * 128 + kp * 16);
                uint32_t sw   = byte ^ ((byte >> 3) & 0x70);
                const size_t go = (size_t)(c0 + n) * K + k0 + kp * 8;
                *(uint4*)(smem + SM_BHI + sw) = *(const uint4*)(Bhi + go);
                *(uint4*)(smem + SM_BLO + sw) = *(const uint4*)(Blo + go);
            }
        }
        __syncthreads();

        if (wid == 0) {
            asm volatile("fence.proxy.async.shared::cta;" ::: "memory");
            if (elect_one_pred()) {
                uint64_t ah = make_desc(sb + SM_AHI);
                uint64_t al = make_desc(sb + SM_ALO);
                uint64_t bh = make_desc(sb + SM_BHI);
                uint64_t bl = make_desc(sb + SM_BLO);
#pragma unroll
                for (int ks = 0; ks < 4; ks++)
                    tc_mma_bf16_ss(tmem, ah + 2 * ks, bh + 2 * ks, idesc,
                                   (ch == 0 && ks == 0) ? 0u : 1u);
#pragma unroll
                for (int ks = 0; ks < 4; ks++)
                    tc_mma_bf16_ss(tmem, ah + 2 * ks, bl + 2 * ks, idesc, 1u);
#pragma unroll
                for (int ks = 0; ks < 4; ks++)
                    tc_mma_bf16_ss(tmem, al + 2 * ks, bh + 2 * ks, idesc, 1u);
                tc_commit(sb + 8);
            }
        }
        mbar_wait(sb + 8, (uint32_t)(ch & 1));
        __syncthreads();
    }

    asm volatile("tcgen05.fence::after_thread_sync;" ::: "memory");

    if (wid < 4) {
        const int m = m0 + wid * 32 + lane;
        const bool valid = m < M;
        for (int cb = 0; cb < 4; cb++) {
            uint32_t r[32];
            TC_LD_32X32B_X32(r, tmem + cb * 32);
            asm volatile("tcgen05.wait::ld.sync.aligned;" ::: "memory");
            if (valid) {
                float* cp = C + (size_t)m * N + c0 + cb * 32;
                if (act == 3) {
                    float ss = 0.f, sd = 0.f;
#pragma unroll
                    for (int c = 0; c < 32; c += 4) {
                        float v0 = __uint_as_float(r[c + 0]);
                        float v1 = __uint_as_float(r[c + 1]);
                        float v2 = __uint_as_float(r[c + 2]);
                        float v3 = __uint_as_float(r[c + 3]);
                        int col = c0 + cb * 32 + c;
                        ss = fmaf(v0, asrc[col + 0], ss); sd = fmaf(v0, adst[col + 0], sd);
                        ss = fmaf(v1, asrc[col + 1], ss); sd = fmaf(v1, adst[col + 1], sd);
                        ss = fmaf(v2, asrc[col + 2], ss); sd = fmaf(v2, adst[col + 2], sd);
                        ss = fmaf(v3, asrc[col + 3], ss); sd = fmaf(v3, adst[col + 3], sd);
                        *(float4*)(cp + c) = make_float4(v0, v1, v2, v3);
                    }
                    int head = (c0 >> 5) + cb;
                    ssrc[m * 8 + head] = ss;
                    sdst[m * 8 + head] = sd;
                } else {
#pragma unroll
                    for (int c = 0; c < 32; c += 4) {
                        int col = c0 + cb * 32 + c;
                        float v0 = __uint_as_float(r[c + 0]) + (bias ? bias[col + 0] : 0.f);
                        float v1 = __uint_as_float(r[c + 1]) + (bias ? bias[col + 1] : 0.f);
                        float v2 = __uint_as_float(r[c + 2]) + (bias ? bias[col + 2] : 0.f);
                        float v3 = __uint_as_float(r[c + 3]) + (bias ? bias[col + 3] : 0.f);
                        if (act == 1) {
                            v0 = tanhf(v0); v1 = tanhf(v1); v2 = tanhf(v2); v3 = tanhf(v3);
                        } else if (act == 2) {
                            v0 = fmaxf(v0, 0.f); v1 = fmaxf(v1, 0.f);
                            v2 = fmaxf(v2, 0.f); v3 = fmaxf(v3, 0.f);
                        }
                        *(float4*)(cp + c) = make_float4(v0, v1, v2, v3);
                    }
                }
            }
        }
        asm volatile("tcgen05.fence::before_thread_sync;" ::: "memory");
    }

    __syncthreads();
    if (wid == 0) {
        if (elect_one_pred()) mbar_inval(sb + 8);
        tc_dealloc(tmem, 128u);
    }

#else
    // =================== FFMA fallback (baseline sm_103) ===================
    float (*As)[128] = (float(*)[128])(smem);            //  8 KB
    float (*Bs)[128] = (float(*)[128])(smem + 8192);     //  8 KB
    float* sred_s = (float*)(smem + 16384);              //  2 KB [128][4]
    float* sred_d = (float*)(smem + 18432);              //  2 KB

    const int tx = tid & 15;
    const int ty = tid >> 4;

    float acc[8][8];
#pragma unroll
    for (int i = 0; i < 8; i++)
#pragma unroll
        for (int j = 0; j < 8; j++) acc[i][j] = 0.f;

    const int ar = tid >> 1;
    const int ac = (tid & 1) * 8;
    const int nl = tid >> 1;
    const int kb = (tid & 1) * 8;

    for (int k0 = 0; k0 < K; k0 += 16) {
        {
            int gr = m0 + ar;
            float4 a0, a1;
            if (gr < M) {
                const float* ap = A + (size_t)gr * K + k0 + ac;
                a0 = *(const float4*)(ap);
                a1 = *(const float4*)(ap + 4);
            } else {
                a0 = make_float4(0.f, 0.f, 0.f, 0.f);
                a1 = a0;
            }
            As[ac + 0][ar] = a0.x; As[ac + 1][ar] = a0.y;
            As[ac + 2][ar] = a0.z; As[ac + 3][ar] = a0.w;
            As[ac + 4][ar] = a1.x; As[ac + 5][ar] = a1.y;
            As[ac + 6][ar] = a1.z; As[ac + 7][ar] = a1.w;
        }
        {
            const size_t go = (size_t)(c0 + nl) * K + k0 + kb;
            uint4 vh = *(const uint4*)(Bhi + go);
            uint4 vl = *(const uint4*)(Blo + go);
            const __nv_bfloat16* hb = (const __nv_bfloat16*)&vh;
            const __nv_bfloat16* lb = (const __nv_bfloat16*)&vl;
#pragma unroll
            for (int j = 0; j < 8; j++)
                Bs[kb + j][nl] = __bfloat162float(hb[j]) + __bfloat162float(lb[j]);
        }
        __syncthreads();
#pragma unroll
        for (int kk = 0; kk < 16; kk++) {
            float a[8], b[8];
            *(float4*)(a)     = *(float4*)&As[kk][ty * 8];
            *(float4*)(a + 4) = *(float4*)&As[kk][ty * 8 + 4];
            *(float4*)(b)     = *(float4*)&Bs[kk][tx * 8];
            *(float4*)(b + 4) = *(float4*)&Bs[kk][tx * 8 + 4];
#pragma unroll
            for (int i = 0; i < 8; i++)
#pragma unroll
                for (int j = 0; j < 8; j++) acc[i][j] = fmaf(a[i], b[j], acc[i][j]);
        }
        __syncthreads();
    }

    const int row0 = m0 + ty * 8;
    const int colg = c0 + tx * 8;

    if (act == 3) {
        for (int idx = tid; idx < 1024; idx += 256) ((float*)(smem + 16384))[idx] = 0.f;
        __syncthreads();
        const int hb = tx >> 2;   // head within block (0..3)
#pragma unroll
        for (int i = 0; i < 8; i++) {
            int r = row0 + i;
            if (r >= M) break;
            float ss = 0.f, sd = 0.f;
            float* cp = C + (size_t)r * N + colg;
#pragma unroll
            for (int j = 0; j < 8; j++) {
                float v = acc[i][j];
                ss = fmaf(v, asrc[colg + j], ss);
                sd = fmaf(v, adst[colg + j], sd);
                cp[j] = v;
            }
            atomicAdd(&sred_s[(ty * 8 + i) * 4 + hb], ss);
            atomicAdd(&sred_d[(ty * 8 + i) * 4 + hb], sd);
        }
        __syncthreads();
        for (int idx = tid; idx < 512; idx += 256) {
            int r = idx >> 2, h = idx & 3;
            int m = m0 + r;
            if (m < M) {
                int head = (c0 >> 5) + h;
                ssrc[m * 8 + head] = sred_s[idx];
                sdst[m * 8 + head] = sred_d[idx];
            }
        }
    } else {
        float bv[8];
#pragma unroll
        for (int j = 0; j < 8; j++) bv[j] = bias ? bias[colg + j] : 0.f;
#pragma unroll
        for (int i = 0; i < 8; i++) {
            int r = row0 + i;
            if (r >= M) break;
            float* cp = C + (size_t)r * N + colg;
#pragma unroll
            for (int j = 0; j < 8; j++) {
                float v = acc[i][j] + bv[j];
                if (act == 1)      v = tanhf(v);
                else if (act == 2) v = fmaxf(v, 0.f);
                cp[j] = v;
            }
        }
    }
#endif
}

// ---------------- CSR build ------------------------------------------------
__global__ __launch_bounds__(256)
void csr_count_kernel(const int* __restrict__ edges)
{
    int idx = blockIdx.x * 256 + threadIdx.x;
    if (idx >= PP * EE) return;
    int p = idx / EE, e = idx - p * EE;
    int d = edges[(size_t)p * 2 * EE + EE + e];
    atomicAdd(&g_count[p * NN + d], 1);
}

__global__ __launch_bounds__(1024)
void csr_scan_kernel()
{
    __shared__ int warp_off[32];
    __shared__ int s_carry;
    const int lane = threadIdx.x & 31;
    const int wid  = threadIdx.x >> 5;

    for (int p = 0; p < PP; p++) {
        const int* counts = g_count  + p * NN;
        int*       indptr = g_indptr + p * (NN + 1);
        int*       cursor = g_cursor + p * NN;
        if (threadIdx.x == 0) s_carry = 0;
        __syncthreads();
        for (int base = 0; base < NN; base += 1024) {
            int i = base + (int)threadIdx.x;
            int v = (i < NN) ? counts[i] : 0;
            int incl = v;
#pragma unroll
            for (int o = 1; o < 32; o <<= 1) {
                int t = __shfl_up_sync(0xFFFFFFFFu, incl, o);
                if (lane >= o) incl += t;
            }
            if (lane == 31) warp_off[wid] = incl;
            __syncthreads();
            if (wid == 0) {
                int ws = warp_off[lane];
                int wincl = ws;
#pragma unroll
                for (int o = 1; o < 32; o <<= 1) {
                    int t = __shfl_up_sync(0xFFFFFFFFu, wincl, o);
                    if (lane >= o) wincl += t;
                }
                warp_off[lane] = wincl - ws;
            }
            __syncthreads();
            int excl = incl - v + warp_off[wid] + s_carry;
            if (i < NN) { indptr[i] = excl; cursor[i] = excl; }
            __syncthreads();
            if (threadIdx.x == 1023) s_carry = excl + v;
            __syncthreads();
        }
        if (threadIdx.x == 0) indptr[NN] = s_carry;
        __syncthreads();
    }
}

__global__ __launch_bounds__(256)
void csr_scatter_kernel(const int* __restrict__ edges)
{
    int idx = blockIdx.x * 256 + threadIdx.x;
    if (idx >= PP * EE) return;
    int p = idx / EE, e = idx - p * EE;
    int s = edges[(size_t)p * 2 * EE + e];
    int d = edges[(size_t)p * 2 * EE + EE + e];
    int pos = atomicAdd(&g_cursor[p * NN + d], 1);
    g_csrc[(size_t)p * EE + pos] = s;
}

__device__ __forceinline__ float leaky02(float v) { return (v > 0.f) ? v : 0.2f * v; }

// ---------------- fused CSR aggregate (proven) -----------------------------
__global__ __launch_bounds__(256)
void gat_aggregate_kernel(const int* __restrict__ indptr, const int* __restrict__ csrc,
                          const float* __restrict__ bias, float* __restrict__ out)
{
    int n    = (blockIdx.x * 256 + threadIdx.x) >> 5;
    int lane = threadIdx.x & 31;
    if (n >= NN) return;

    const int beg = indptr[n];
    const int end = indptr[n + 1];

    float sd = 0.f, eself = 0.f;
    if (lane < 8) {
        sd    = g_sdst[n * 8 + lane];
        eself = leaky02(g_ssrc[n * 8 + lane] + sd);
    }
    float m = eself;
    for (int ptr = beg; ptr < end; ptr++) {
        int s = csrc[ptr];
        if (lane < 8)
            m = fmaxf(m, leaky02(g_ssrc[s * 8 + lane] + sd));
    }

    float den = (lane < 8) ? __expf(eself - m) : 0.f;
    const float exself = den;
    float accv[8];
#pragma unroll
    for (int k = 0; k < 8; k++) accv[k] = 0.f;

    for (int ptr = beg; ptr < end; ptr++) {
        int s = csrc[ptr];
        float ex = 0.f;
        if (lane < 8) {
            ex = __expf(leaky02(g_ssrc[s * 8 + lane] + sd) - m);
            den += ex;
        }
        float exh[8];
#pragma unroll
        for (int k = 0; k < 8; k++) exh[k] = __shfl_sync(0xFFFFFFFFu, ex, k);
        const float* hp = g_hp + (size_t)s * F;
#pragma unroll
        for (int k = 0; k < 8; k++)
            accv[k] = fmaf(exh[k], hp[k * 32 + lane], accv[k]);
    }

    float exsh[8], dh[8];
#pragma unroll
    for (int k = 0; k < 8; k++) {
        exsh[k] = __shfl_sync(0xFFFFFFFFu, exself, k);
        dh[k]   = __shfl_sync(0xFFFFFFFFu, den, k);
    }
    const float* hpn = g_hp + (size_t)n * F;
    float*       op  = out  + (size_t)n * F;
#pragma unroll
    for (int k = 0; k < 8; k++) {
        int idx = k * 32 + lane;
        float v = (accv[k] + exsh[k] * hpn[idx]) / dh[k] + bias[idx];
        v = (v > 0.f) ? v : expm1f(v);
        op[idx] = v;
    }
}

// ---------------- semantic score: sc[n,p] = t1[n,:] . W2 -------------------
__global__ __launch_bounds__(256)
void sem_score_kernel(const float* __restrict__ W2, int p)
{
    int n    = (blockIdx.x * 256 + threadIdx.x) >> 5;
    int lane = threadIdx.x & 31;
    if (n >= NN) return;
    float ssum = 0.f;
#pragma unroll
    for (int k = 0; k < 4; k++) {
        int idx = k * 32 + lane;
        ssum = fmaf(g_t1[n * F1 + idx], W2[idx], ssum);
    }
#pragma unroll
    for (int o = 16; o > 0; o >>= 1) ssum += __shfl_xor_sync(0xFFFFFFFFu, ssum, o);
    if (lane == 0) g_sc[n * PP + p] = ssum;
}

// ---------------- semantic softmax + weighted combine ----------------------
__global__ __launch_bounds__(256)
void sem_combine_kernel()
{
    int n    = (blockIdx.x * 256 + threadIdx.x) >> 5;
    int lane = threadIdx.x & 31;
    if (n >= NN) return;
    float s0 = g_sc[n * PP + 0], s1 = g_sc[n * PP + 1], s2 = g_sc[n * PP + 2];
    float mx = fmaxf(s0, fmaxf(s1, s2));
    float w0 = __expf(s0 - mx), w1 = __expf(s1 - mx), w2 = __expf(s2 - mx);
    float inv = 1.f / (w0 + w1 + w2);
    w0 *= inv; w1 *= inv; w2 *= inv;
    const float* e0 = g_emb + (size_t)n * F;
    const float* e1 = g_emb + (size_t)(NN + n) * F;
    const float* e2 = g_emb + (size_t)(2 * NN + n) * F;
    float* zp = g_z + (size_t)n * F;
#pragma unroll
    for (int k = 0; k < 8; k++) {
        int idx = k * 32 + lane;
        zp[idx] = w0 * e0[idx] + w1 * e1[idx] + w2 * e2[idx];
    }
}

// ---------------- classifier head: logits = t2 @ W2 + b2 -------------------
__global__ __launch_bounds__(256)
void cls_out_kernel(const float* __restrict__ W2, const float* __restrict__ b2,
                    float* __restrict__ out)
{
    int n    = (blockIdx.x * 256 + threadIdx.x) >> 5;
    int lane = threadIdx.x & 31;
    if (n >= NN) return;
    float c0 = 0.f, c1 = 0.f;
#pragma unroll
    for (int k = 0; k < 4; k++) {
        int idx = k * 32 + lane;
        float t = g_t2[n * F1 + idx];
        c0 = fmaf(t, W2[idx * 2 + 0], c0);
        c1 = fmaf(t, W2[idx * 2 + 1], c1);
    }
#pragma unroll
    for (int o = 16; o > 0; o >>= 1) {
        c0 += __shfl_xor_sync(0xFFFFFFFFu, c0, o);
        c1 += __shfl_xor_sync(0xFFFFFFFFu, c1, o);
    }
    if (lane == 0) {
        out[n * 2 + 0] = c0 + b2[0];
        out[n * 2 + 1] = c1 + b2[1];
    }
}

// ---------------- driver ---------------------------------------------------
extern "C" void kernel_launch(void* const* d_in, const int* in_sizes, int n_in,
                              void* d_out, int out_size)
{
    const float* x        = (const float*)d_in[0];
    const int*   edges    = (const int*)  d_in[1];
    const float* proj_W   = (const float*)d_in[2];
    const float* proj_b   = (const float*)d_in[3];
    const float* gat_W    = (const float*)d_in[4];
    const float* gat_asrc = (const float*)d_in[5];
    const float* gat_adst = (const float*)d_in[6];
    const float* gat_b    = (const float*)d_in[7];
    const float* sem_W1   = (const float*)d_in[8];
    const float* sem_b1   = (const float*)d_in[9];
    const float* sem_W2   = (const float*)d_in[10];
    const float* cls_W1   = (const float*)d_in[11];
    const float* cls_b1   = (const float*)d_in[12];
    const float* cls_W2   = (const float*)d_in[13];
    const float* cls_b2   = (const float*)d_in[14];
    float* out = (float*)d_out;

    float *h0, *h, *hp, *emb, *t1, *t2, *z, *ssrc, *sdst;
    int *countp, *indptr, *csrc;
    __nv_bfloat16* wt;
    cudaGetSymbolAddress((void**)&h0,  g_h0);
    cudaGetSymbolAddress((void**)&h,   g_h);
    cudaGetSymbolAddress((void**)&hp,  g_hp);
    cudaGetSymbolAddress((void**)&emb, g_emb);
    cudaGetSymbolAddress((void**)&t1,  g_t1);
    cudaGetSymbolAddress((void**)&t2,  g_t2);
    cudaGetSymbolAddress((void**)&z,   g_z);
    cudaGetSymbolAddress((void**)&ssrc, g_ssrc);
    cudaGetSymbolAddress((void**)&sdst, g_sdst);
    cudaGetSymbolAddress((void**)&countp, g_count);
    cudaGetSymbolAddress((void**)&indptr, g_indptr);
    cudaGetSymbolAddress((void**)&csrc,   g_csrc);
    cudaGetSymbolAddress((void**)&wt,     g_wt);

    const int SMEM = 66560;   // max of both paths
    cudaFuncSetAttribute(gemm_tc, cudaFuncAttributeMaxDynamicSharedMemorySize, SMEM);

    const int MT = (NN + 127) / 128;          // 391 M-tiles
    const int nodeWarpBlocks = (NN + 7) / 8;
    const int allEdgeBlocks  = (PP * EE + 255) / 256;

    // --- weight split/transposition (bf16 hi/lo, [N][K]) -------------------
    conv_w_kernel<<<(128 * 256 + 255) / 256, 256>>>(proj_W, wt, wt + 32768, 128, 256);
    for (int li = 0; li < 6; li++) {
        __nv_bfloat16* base = wt + 65536 + (size_t)li * 131072;
        conv_w_kernel<<<(256 * 256 + 255) / 256, 256>>>(gat_W + (size_t)li * 65536,
                                                        base, base + 65536, 256, 256);
    }
    conv_w_kernel<<<(256 * 128 + 255) / 256, 256>>>(sem_W1, wt + 851968, wt + 884736, 256, 128);
    conv_w_kernel<<<(256 * 128 + 255) / 256, 256>>>(cls_W1, wt + 917504, wt + 950272, 256, 128);

    // --- CSR build ----------------------------------------------------------
    cudaMemsetAsync(countp, 0, sizeof(int) * PP * NN);
    csr_count_kernel<<<allEdgeBlocks, 256>>>(edges);
    csr_scan_kernel<<<1, 1024>>>();
    csr_scatter_kernel<<<allEdgeBlocks, 256>>>(edges);

    // h0 = x @ proj_W + proj_b
    gemm_tc<<<dim3(2, MT), 256, SMEM>>>(x, wt, wt + 32768, proj_b, h0,
                                        NN, 128, 256, 0, nullptr, nullptr, nullptr, nullptr);

    for (int p = 0; p < PP; p++) {
        const int* ip = indptr + (size_t)p * (NN + 1);
        const int* cs = csrc   + (size_t)p * EE;
        const float* hin = h0;
        for (int l = 0; l < 2; l++) {
            int li = p * 2 + l;
            __nv_bfloat16* wb = wt + 65536 + (size_t)li * 131072;
            const float* as = gat_asrc + (size_t)li * Hh * DHd;
            const float* ad = gat_adst + (size_t)li * Hh * DHd;
            const float* bb = gat_b    + (size_t)li * F;

            // hp = hin @ W ; fused s_src/s_dst in epilogue (act=3)
            gemm_tc<<<dim3(2, MT), 256, SMEM>>>(hin, wb, wb + 65536, nullptr, hp,
                                                NN, 256, 256, 3, as, ad, ssrc, sdst);
            float* obuf = (l == 0) ? h : (emb + (size_t)p * NN * F);
            gat_aggregate_kernel<<<nodeWarpBlocks, 256>>>(ip, cs, bb, obuf);
            hin = h;
        }
    }

    // semantic attention
    for (int p = 0; p < PP; p++) {
        gemm_tc<<<dim3(1, MT), 256, SMEM>>>(emb + (size_t)p * NN * F, wt + 851968, wt + 884736,
                                            sem_b1, t1, NN, 256, 128, 1,
                                            nullptr, nullptr, nullptr, nullptr);
        sem_score_kernel<<<nodeWarpBlocks, 256>>>(sem_W2, p);
    }
    sem_combine_kernel<<<nodeWarpBlocks, 256>>>();

    // classifier
    gemm_tc<<<dim3(1, MT), 256, SMEM>>>(z, wt + 917504, wt + 950272, cls_b1, t2,
                                        NN, 256, 128, 2, nullptr, nullptr, nullptr, nullptr);
    cls_out_kernel<<<nodeWarpBlocks, 256>>>(cls_W2, cls_b2, out);
}